// round 16
// baseline (speedup 1.0000x reference)
#include <cuda_runtime.h>
#include <cuda_fp16.h>
#include <cstdint>

// Problem dims
#define M_TOTAL 16384      // 8 * 2048
#define N_TOTAL 4096       // OUT_FEATURES
#define K_TOTAL 4096       // IN_FEATURES

// GEMM tiling: BK=64, 3-stage, warp-specialized producer, 64x64 warp tiles
#define BM 128
#define BN 128
#define BK 64
#define STAGES 3
#define KT (K_TOTAL / BK)        // 64
#define PITCH 144                 // 128B data + 16B pad per row (conflict-free ldsm)

#define A_STAGE_B (BM * PITCH)              // 18432
#define B_STAGE_B (BN * PITCH)              // 18432
#define STAGE_B   (A_STAGE_B + B_STAGE_B)   // 36864
#define MBAR_OFF  (STAGES * STAGE_B)        // 110592
#define MBAR_FULL(s)  (MBAR_OFF + (s) * 8)
#define MBAR_EMPTY(s) (MBAR_OFF + 24 + (s) * 8)
#define SMEM_TOTAL (MBAR_OFF + 64)          // 110656 -> 2 CTAs/SM

#define GRID_X 32                 // N tiles
#define GRID_YG 128               // M tiles (GEMM rows of the grid)
#define N_CTAS (GRID_X * GRID_YG) // 4096 GEMM CTAs (converters excluded)

// Static scratch: fp16 copies of x and dequantized W
__device__ __half g_Xh[(size_t)M_TOTAL * K_TOTAL];   // 128 MB
__device__ __half g_Wh[(size_t)N_TOTAL * K_TOTAL];   // 32 MB

// Readiness flags (self-resetting each launch; zero-initialized)
__device__ int g_wrdy[GRID_X];    // W chunk c (rows 128c..+128) converted
__device__ int g_xrdy[GRID_YG];   // x row-block b (rows 128b..+128) converted
__device__ int g_done = 0;        // finished GEMM CTAs

__constant__ float c_nf4[16] = {
    -1.0f, -0.6961928009986877f, -0.5250730514526367f, -0.39491748809814453f,
    -0.28444138169288635f, -0.18477343022823334f, -0.09105003625154495f, 0.0f,
    0.07958029955625534f, 0.16093020141124725f, 0.24611230194568634f,
    0.33791524171829224f, 0.44070982933044434f, 0.5626170039176941f,
    0.7229568362236023f, 1.0f};

__device__ __forceinline__ uint32_t smem_u32(const void* p) {
    return (uint32_t)__cvta_generic_to_shared(p);
}
__device__ __forceinline__ void cp_async16(uint32_t dst, const void* src) {
    asm volatile("cp.async.cg.shared.global [%0], [%1], 16;" :: "r"(dst), "l"(src));
}
__device__ __forceinline__ void ldsm_x4(uint32_t* r, uint32_t a) {
    asm volatile("ldmatrix.sync.aligned.m8n8.x4.shared.b16 {%0,%1,%2,%3}, [%4];"
                 : "=r"(r[0]), "=r"(r[1]), "=r"(r[2]), "=r"(r[3]) : "r"(a));
}
__device__ __forceinline__ void mbar_init(uint32_t a, uint32_t cnt) {
    asm volatile("mbarrier.init.shared.b64 [%0], %1;" :: "r"(a), "r"(cnt) : "memory");
}
__device__ __forceinline__ void mbar_arrive(uint32_t a) {
    asm volatile("mbarrier.arrive.shared.b64 _, [%0];" :: "r"(a) : "memory");
}
__device__ __forceinline__ void cp_async_arrive(uint32_t a) {
    asm volatile("cp.async.mbarrier.arrive.noinc.shared.b64 [%0];" :: "r"(a) : "memory");
}
__device__ __forceinline__ void mbar_wait(uint32_t a, uint32_t parity) {
    asm volatile(
        "{\n\t.reg .pred P;\n\t"
        "WL%=:\n\t"
        "mbarrier.try_wait.parity.acquire.cta.shared::cta.b64 P, [%0], %1, 0x989680;\n\t"
        "@!P bra WL%=;\n\t}"
        :: "r"(a), "r"(parity) : "memory");
}
__device__ __forceinline__ int ld_acq(const int* p) {
    int v;
    asm volatile("ld.acquire.gpu.global.b32 %0, [%1];" : "=r"(v) : "l"(p) : "memory");
    return v;
}

// ---------------------------------------------------------------------------
// Fused kernel with DEDICATED converter CTAs (by==0, bids 0..31, run first).
//   Converter c: dequant W rows [128c,+128) -> g_wrdy[c]=1;
//                then x blocks {c,32+c,64+c,96+c} -> g_xrdy[b]=1 per pass.
//   GEMM CTA (bx, by>=1): bm=(by-1)*128; producer waits for g_wrdy[bx] and
//   g_xrdy[by-1], then runs the R12 warp-specialized mainloop unchanged.
// ---------------------------------------------------------------------------
__global__ void __launch_bounds__(160, 2)
gemm_fused_kernel(const float* __restrict__ x,
                  const int* __restrict__ wp,
                  const float* __restrict__ scale,
                  const float* __restrict__ bias,
                  float* __restrict__ C) {
    extern __shared__ __align__(16) char smem[];
    const uint32_t sb = smem_u32(smem);

    const int tid  = threadIdx.x;
    const int lane = tid & 31;
    const int warp = tid >> 5;
    const int bx = blockIdx.x;
    const int by = blockIdx.y;

    if (by == 0) {
        // ================= converter CTA c = bx =================
        const int c = bx;
        // --- W chunk: rows [128c, +128): 65536 int4 of packed nibbles ---
        {
            const int4* s4 = (const int4*)(wp + (size_t)(128 * c) * (K_TOTAL / 2));
            uint4* d4 = (uint4*)(g_Wh + (size_t)(128 * c) * K_TOTAL);
            const float s = __ldg(scale);
#pragma unroll 4
            for (int i = tid; i < 65536; i += 160) {
                int4 v = s4[i];
                int vv[4] = {v.x, v.y, v.z, v.w};
                __align__(16) __half h[8];
#pragma unroll
                for (int j = 0; j < 4; j++) {
                    h[2 * j]     = __float2half(c_nf4[vv[j] & 15] * s);
                    h[2 * j + 1] = __float2half(c_nf4[(vv[j] >> 4) & 15] * s);
                }
                d4[i] = *(const uint4*)h;
            }
        }
        __syncthreads();
        if (tid == 0) {
            __threadfence();
            atomicExch(&g_wrdy[c], 1);
        }
        // --- x blocks: passes publish progressively ---
#pragma unroll 1
        for (int p = 0; p < 4; p++) {
            const int b = 32 * p + c;
            const float4* xs = (const float4*)(x + (size_t)(128 * b) * K_TOTAL);
            uint2* xd = (uint2*)(g_Xh + (size_t)(128 * b) * K_TOTAL);
#pragma unroll 4
            for (int i = tid; i < 131072; i += 160) {
                float4 v = xs[i];
                __half2 h0 = __floats2half2_rn(v.x, v.y);
                __half2 h1 = __floats2half2_rn(v.z, v.w);
                uint2 o;
                o.x = *(uint32_t*)&h0;
                o.y = *(uint32_t*)&h1;
                xd[i] = o;
            }
            __syncthreads();
            if (tid == 0) {
                __threadfence();
                atomicExch(&g_xrdy[b], 1);
            }
        }
        return;
    }

    // ================= GEMM CTA =================
    const int bym = by - 1;
    const int bm = bym * BM;
    const int bn = bx * BN;
    const __half* xh = g_Xh;
    const __half* wh = g_Wh;

    if (tid == 0) {
#pragma unroll
        for (int s = 0; s < STAGES; s++) {
            mbar_init(sb + MBAR_FULL(s), 32);   // 32 producer-lane async arrivals
            mbar_init(sb + MBAR_EMPTY(s), 4);   // 4 consumer warps (1 lane each)
        }
    }
    __syncthreads();

    if (warp == 4) {
        // ================= producer warp =================
        if (lane == 0) {
            while (ld_acq(&g_wrdy[bx]) == 0) __nanosleep(64);
            while (ld_acq(&g_xrdy[bym]) == 0) __nanosleep(64);
        }
        __syncwarp();

        const int r0 = lane >> 3;             // 0..3
        const int cc = (lane & 7) * 8;        // halves: 0..56
        const __half* Ag = xh + (size_t)(bm + r0) * K_TOTAL + cc;
        const __half* Bg = wh + (size_t)(bn + r0) * K_TOTAL + cc;
        const uint32_t sA = sb + r0 * PITCH + cc * 2;
        const uint32_t sB = sA + A_STAGE_B;

        int s = 0, r = 0;
#pragma unroll 1
        for (int kt = 0; kt < KT; kt++) {
            if (kt >= STAGES)
                mbar_wait(sb + MBAR_EMPTY(s), (r - 1) & 1);
            const uint32_t so = (uint32_t)s * STAGE_B;
            const size_t g = (size_t)kt * BK;
            const __half* a = Ag + g;
            const __half* b = Bg + g;
#pragma unroll 8
            for (int j = 0; j < 32; j++)       // A rows r0 + 4j
                cp_async16(sA + so + j * (4 * PITCH), a + (size_t)j * 4 * K_TOTAL);
#pragma unroll 8
            for (int j = 0; j < 32; j++)       // B rows r0 + 4j
                cp_async16(sB + so + j * (4 * PITCH), b + (size_t)j * 4 * K_TOTAL);
            cp_async_arrive(sb + MBAR_FULL(s));
            if (++s == STAGES) { s = 0; r++; }
        }
    } else {
        // ================= consumer warps 0..3 (2x2 grid of 64x64 tiles) ==
        const int wm = (warp >> 1) * 64;   // 0 or 64
        const int wn = (warp & 1) * 64;    // 0 or 64

        float acc[4][8][4];
#pragma unroll
        for (int i = 0; i < 4; i++)
#pragma unroll
            for (int j = 0; j < 8; j++)
#pragma unroll
                for (int r = 0; r < 4; r++) acc[i][j][r] = 0.f;

        const int arow  = lane & 15;
        const int aoff8 = (lane >> 4) * 8;
        const int brow  = (lane & 7) + ((lane >> 4) & 1) * 8;
        const int boff8 = ((lane >> 3) & 1) * 8;
        const uint32_t a_base = sb + (wm + arow) * PITCH + aoff8 * 2;
        const uint32_t b_base = sb + A_STAGE_B + (wn + brow) * PITCH + boff8 * 2;

        int s = 0, ph = 0;
#pragma unroll 1
        for (int kt = 0; kt < KT; kt++) {
            mbar_wait(sb + MBAR_FULL(s), ph);
            const uint32_t boff = (uint32_t)s * STAGE_B;

#pragma unroll
            for (int ks = 0; ks < 4; ks++) {
                uint32_t ar[4][4], br[8][2];
#pragma unroll
                for (int mi = 0; mi < 4; mi++)
                    ldsm_x4(ar[mi], a_base + boff + ks * 32 + mi * (16 * PITCH));
#pragma unroll
                for (int nb = 0; nb < 4; nb++) {
                    uint32_t r[4];
                    ldsm_x4(r, b_base + boff + ks * 32 + nb * (16 * PITCH));
                    br[nb * 2][0] = r[0]; br[nb * 2][1] = r[1];
                    br[nb * 2 + 1][0] = r[2]; br[nb * 2 + 1][1] = r[3];
                }
                if (ks == 3 && lane == 0)
                    mbar_arrive(sb + MBAR_EMPTY(s));
#pragma unroll
                for (int mi = 0; mi < 4; mi++)
#pragma unroll
                    for (int ni = 0; ni < 8; ni++)
                        asm volatile(
                            "mma.sync.aligned.m16n8k16.row.col.f32.f16.f16.f32 "
                            "{%0,%1,%2,%3}, {%4,%5,%6,%7}, {%8,%9}, {%0,%1,%2,%3};"
                            : "+f"(acc[mi][ni][0]), "+f"(acc[mi][ni][1]),
                              "+f"(acc[mi][ni][2]), "+f"(acc[mi][ni][3])
                            : "r"(ar[mi][0]), "r"(ar[mi][1]), "r"(ar[mi][2]), "r"(ar[mi][3]),
                              "r"(br[ni][0]), "r"(br[ni][1]));
            }

            if (++s == STAGES) { s = 0; ph ^= 1; }
        }

        // --- epilogue: bias add + fp32 store
#pragma unroll
        for (int mi = 0; mi < 4; mi++) {
            const int row0 = bm + wm + mi * 16 + (lane >> 2);
#pragma unroll
            for (int ni = 0; ni < 8; ni++) {
                const int col = bn + wn + ni * 8 + (lane & 3) * 2;
                const float b0 = bias[col];
                const float b1 = bias[col + 1];
                float2 v0 = make_float2(acc[mi][ni][0] + b0, acc[mi][ni][1] + b1);
                float2 v1 = make_float2(acc[mi][ni][2] + b0, acc[mi][ni][3] + b1);
                *(float2*)&C[(size_t)row0 * N_TOTAL + col]       = v0;
                *(float2*)&C[(size_t)(row0 + 8) * N_TOTAL + col] = v1;
            }
        }
    }

    // ---- self-reset of global flags (last GEMM CTA) ----
    __syncthreads();
    if (tid == 0) {
        int old = atomicAdd(&g_done, 1);
        if (old == N_CTAS - 1) {
#pragma unroll 4
            for (int i = 0; i < GRID_X; i++) g_wrdy[i] = 0;
#pragma unroll 4
            for (int i = 0; i < GRID_YG; i++) g_xrdy[i] = 0;
            g_done = 0;
            __threadfence();
        }
    }
}

// ---------------------------------------------------------------------------
// Launch: single fused kernel, converters in grid row 0.
// ---------------------------------------------------------------------------
extern "C" void kernel_launch(void* const* d_in, const int* in_sizes, int n_in,
                              void* d_out, int out_size) {
    const float* x     = (const float*)d_in[0];
    const int*   wp    = (const int*)d_in[1];
    const float* scale = (const float*)d_in[2];
    const float* bias  = (const float*)d_in[3];
    float*       out   = (float*)d_out;

    cudaFuncSetAttribute(gemm_fused_kernel,
                         cudaFuncAttributeMaxDynamicSharedMemorySize, SMEM_TOTAL);
    dim3 grid(GRID_X, GRID_YG + 1);   // (32, 129); row 0 = converters
    gemm_fused_kernel<<<grid, 160, SMEM_TOTAL>>>(x, wp, scale, bias, out);
}

// round 17
// speedup vs baseline: 1.2661x; 1.2661x over previous
#include <cuda_runtime.h>
#include <cuda_fp16.h>
#include <cstdint>

// Problem dims
#define M_TOTAL 16384      // 8 * 2048
#define N_TOTAL 4096       // OUT_FEATURES
#define K_TOTAL 4096       // IN_FEATURES

// GEMM tiling: BK=64, 3-stage, warp-specialized producer, 64x64 warp tiles
#define BM 128
#define BN 128
#define BK 64
#define STAGES 3
#define KT (K_TOTAL / BK)        // 64
#define PITCH 144                 // 128B data + 16B pad per row (conflict-free ldsm)

#define A_STAGE_B (BM * PITCH)              // 18432
#define B_STAGE_B (BN * PITCH)              // 18432
#define STAGE_B   (A_STAGE_B + B_STAGE_B)   // 36864
#define MBAR_OFF  (STAGES * STAGE_B)        // 110592
#define MBAR_FULL(s)  (MBAR_OFF + (s) * 8)
#define MBAR_EMPTY(s) (MBAR_OFF + 24 + (s) * 8)
#define SMEM_TOTAL (MBAR_OFF + 64)          // 110656 -> 2 CTAs/SM

// Static scratch: fp16 copies of x and dequantized W
__device__ __half g_Xh[(size_t)M_TOTAL * K_TOTAL];   // 128 MB
__device__ __half g_Wh[(size_t)N_TOTAL * K_TOTAL];   // 32 MB

__constant__ float c_nf4[16] = {
    -1.0f, -0.6961928009986877f, -0.5250730514526367f, -0.39491748809814453f,
    -0.28444138169288635f, -0.18477343022823334f, -0.09105003625154495f, 0.0f,
    0.07958029955625534f, 0.16093020141124725f, 0.24611230194568634f,
    0.33791524171829224f, 0.44070982933044434f, 0.5626170039176941f,
    0.7229568362236023f, 1.0f};

__device__ __forceinline__ uint32_t smem_u32(const void* p) {
    return (uint32_t)__cvta_generic_to_shared(p);
}
__device__ __forceinline__ void cp_async16(uint32_t dst, const void* src) {
    asm volatile("cp.async.cg.shared.global [%0], [%1], 16;" :: "r"(dst), "l"(src));
}
__device__ __forceinline__ void ldsm_x4(uint32_t* r, uint32_t a) {
    asm volatile("ldmatrix.sync.aligned.m8n8.x4.shared.b16 {%0,%1,%2,%3}, [%4];"
                 : "=r"(r[0]), "=r"(r[1]), "=r"(r[2]), "=r"(r[3]) : "r"(a));
}
__device__ __forceinline__ void mbar_init(uint32_t a, uint32_t cnt) {
    asm volatile("mbarrier.init.shared.b64 [%0], %1;" :: "r"(a), "r"(cnt) : "memory");
}
__device__ __forceinline__ void mbar_arrive(uint32_t a) {
    asm volatile("mbarrier.arrive.shared.b64 _, [%0];" :: "r"(a) : "memory");
}
__device__ __forceinline__ void cp_async_arrive(uint32_t a) {
    asm volatile("cp.async.mbarrier.arrive.noinc.shared.b64 [%0];" :: "r"(a) : "memory");
}
__device__ __forceinline__ void mbar_wait(uint32_t a, uint32_t parity) {
    asm volatile(
        "{\n\t.reg .pred P;\n\t"
        "WL%=:\n\t"
        "mbarrier.try_wait.parity.acquire.cta.shared::cta.b64 P, [%0], %1, 0x989680;\n\t"
        "@!P bra WL%=;\n\t}"
        :: "r"(a), "r"(parity) : "memory");
}

// ---------------------------------------------------------------------------
// Merged prep (high-MLP): x fp32->fp16 AND NF4 dequant of W, one launch.
//   blocks [0, XB):  x convert — each thread 2 independent float4 (front-batched)
//   blocks [XB, XB+WB): W dequant — each thread 2 independent int4
// ---------------------------------------------------------------------------
#define XB 32768   // 32768 * 256 threads * 2 float4 = 16777216 float4 = all of x
#define WB 4096    // 4096 * 256 threads * 2 int4 = 2097152 int4 = all of wp
__global__ void __launch_bounds__(256)
prep_kernel(const float* __restrict__ x,
            const int* __restrict__ wp,
            const float* __restrict__ scale,
            __half* __restrict__ xh,
            __half* __restrict__ wh) {
    if (blockIdx.x < XB) {
        // two independent float4 loads issued back-to-back (MLP=2)
        const long long base = (long long)blockIdx.x * 512 + threadIdx.x;
        const float4* s4 = (const float4*)x;
        float4 v0 = s4[base];
        float4 v1 = s4[base + 256];
        uint2 o0, o1;
        {
            __half2 h0 = __floats2half2_rn(v0.x, v0.y);
            __half2 h1 = __floats2half2_rn(v0.z, v0.w);
            o0.x = *(uint32_t*)&h0; o0.y = *(uint32_t*)&h1;
        }
        {
            __half2 h0 = __floats2half2_rn(v1.x, v1.y);
            __half2 h1 = __floats2half2_rn(v1.z, v1.w);
            o1.x = *(uint32_t*)&h0; o1.y = *(uint32_t*)&h1;
        }
        uint2* d2 = (uint2*)xh;
        d2[base] = o0;
        d2[base + 256] = o1;
    } else {
        const long long base = (long long)(blockIdx.x - XB) * 512 + threadIdx.x;
        const float s = __ldg(scale);
        const int4* s4 = (const int4*)wp;
        int4 v0 = s4[base];
        int4 v1 = s4[base + 256];
        uint4* d4 = (uint4*)wh;
        {
            int vv[4] = {v0.x, v0.y, v0.z, v0.w};
            __align__(16) __half h[8];
#pragma unroll
            for (int j = 0; j < 4; j++) {
                h[2 * j]     = __float2half(c_nf4[vv[j] & 15] * s);
                h[2 * j + 1] = __float2half(c_nf4[(vv[j] >> 4) & 15] * s);
            }
            d4[base] = *(const uint4*)h;
        }
        {
            int vv[4] = {v1.x, v1.y, v1.z, v1.w};
            __align__(16) __half h[8];
#pragma unroll
            for (int j = 0; j < 4; j++) {
                h[2 * j]     = __float2half(c_nf4[vv[j] & 15] * s);
                h[2 * j + 1] = __float2half(c_nf4[(vv[j] >> 4) & 15] * s);
            }
            d4[base + 256] = *(const uint4*)h;
        }
    }
}

// ---------------------------------------------------------------------------
// GEMM: C[M,N] = A[M,K](fp16) * B[N,K]^T(fp16) + bias, fp32 out.
// 128x128 CTA tile. Warps 0-3: consumers (64x64 warp tiles, 2x2 grid).
// Warp 4: cp.async producer. mbarrier pipeline, no __syncthreads in mainloop.
// 160 threads, 2 CTAs/SM.  (R12 — best verified configuration.)
// ---------------------------------------------------------------------------
__global__ void __launch_bounds__(160, 2)
gemm_f16_kernel(const __half* __restrict__ A, const __half* __restrict__ Bm,
                const float* __restrict__ bias, float* __restrict__ C) {
    extern __shared__ __align__(16) char smem[];
    const uint32_t sb = smem_u32(smem);

    const int tid  = threadIdx.x;
    const int lane = tid & 31;
    const int warp = tid >> 5;
    const int bm = blockIdx.y * BM;
    const int bn = blockIdx.x * BN;

    if (tid == 0) {
#pragma unroll
        for (int s = 0; s < STAGES; s++) {
            mbar_init(sb + MBAR_FULL(s), 32);   // 32 producer-lane async arrivals
            mbar_init(sb + MBAR_EMPTY(s), 4);   // 4 consumer warps (1 lane each)
        }
    }
    __syncthreads();

    if (warp == 4) {
        // ================= producer warp =================
        const int r0 = lane >> 3;             // 0..3
        const int cc = (lane & 7) * 8;        // halves: 0..56
        const __half* Ag = A  + (size_t)(bm + r0) * K_TOTAL + cc;
        const __half* Bg = Bm + (size_t)(bn + r0) * K_TOTAL + cc;
        const uint32_t sA = sb + r0 * PITCH + cc * 2;
        const uint32_t sB = sA + A_STAGE_B;

        int s = 0, r = 0;
#pragma unroll 1
        for (int kt = 0; kt < KT; kt++) {
            if (kt >= STAGES)
                mbar_wait(sb + MBAR_EMPTY(s), (r - 1) & 1);
            const uint32_t so = (uint32_t)s * STAGE_B;
            const size_t g = (size_t)kt * BK;
            const __half* a = Ag + g;
            const __half* b = Bg + g;
#pragma unroll 8
            for (int j = 0; j < 32; j++)       // A rows r0 + 4j
                cp_async16(sA + so + j * (4 * PITCH), a + (size_t)j * 4 * K_TOTAL);
#pragma unroll 8
            for (int j = 0; j < 32; j++)       // B rows r0 + 4j
                cp_async16(sB + so + j * (4 * PITCH), b + (size_t)j * 4 * K_TOTAL);
            cp_async_arrive(sb + MBAR_FULL(s));
            if (++s == STAGES) { s = 0; r++; }
        }
        return;
    }

    // ================= consumer warps 0..3 (2x2 grid of 64x64 tiles) ======
    const int wm = (warp >> 1) * 64;   // 0 or 64
    const int wn = (warp & 1) * 64;    // 0 or 64

    float acc[4][8][4];
#pragma unroll
    for (int i = 0; i < 4; i++)
#pragma unroll
        for (int j = 0; j < 8; j++)
#pragma unroll
            for (int r = 0; r < 4; r++) acc[i][j][r] = 0.f;

    // ldmatrix per-lane bases (stage 0)
    const int arow  = lane & 15;
    const int aoff8 = (lane >> 4) * 8;
    const int brow  = (lane & 7) + ((lane >> 4) & 1) * 8;
    const int boff8 = ((lane >> 3) & 1) * 8;
    const uint32_t a_base = sb + (wm + arow) * PITCH + aoff8 * 2;
    const uint32_t b_base = sb + A_STAGE_B + (wn + brow) * PITCH + boff8 * 2;

    int s = 0, ph = 0;
#pragma unroll 1
    for (int kt = 0; kt < KT; kt++) {
        mbar_wait(sb + MBAR_FULL(s), ph);
        const uint32_t boff = (uint32_t)s * STAGE_B;

#pragma unroll
        for (int ks = 0; ks < 4; ks++) {
            uint32_t ar[4][4], br[8][2];
#pragma unroll
            for (int mi = 0; mi < 4; mi++)
                ldsm_x4(ar[mi], a_base + boff + ks * 32 + mi * (16 * PITCH));
#pragma unroll
            for (int nb = 0; nb < 4; nb++) {
                uint32_t r[4];
                ldsm_x4(r, b_base + boff + ks * 32 + nb * (16 * PITCH));
                br[nb * 2][0] = r[0]; br[nb * 2][1] = r[1];
                br[nb * 2 + 1][0] = r[2]; br[nb * 2 + 1][1] = r[3];
            }
            if (ks == 3 && lane == 0)          // all this warp's LDSM for stage done
                mbar_arrive(sb + MBAR_EMPTY(s));
#pragma unroll
            for (int mi = 0; mi < 4; mi++)
#pragma unroll
                for (int ni = 0; ni < 8; ni++)
                    asm volatile(
                        "mma.sync.aligned.m16n8k16.row.col.f32.f16.f16.f32 "
                        "{%0,%1,%2,%3}, {%4,%5,%6,%7}, {%8,%9}, {%0,%1,%2,%3};"
                        : "+f"(acc[mi][ni][0]), "+f"(acc[mi][ni][1]),
                          "+f"(acc[mi][ni][2]), "+f"(acc[mi][ni][3])
                        : "r"(ar[mi][0]), "r"(ar[mi][1]), "r"(ar[mi][2]), "r"(ar[mi][3]),
                          "r"(br[ni][0]), "r"(br[ni][1]));
        }

        if (++s == STAGES) { s = 0; ph ^= 1; }
    }

    // --- epilogue: bias add + fp32 store
#pragma unroll
    for (int mi = 0; mi < 4; mi++) {
        const int row0 = bm + wm + mi * 16 + (lane >> 2);
#pragma unroll
        for (int ni = 0; ni < 8; ni++) {
            const int col = bn + wn + ni * 8 + (lane & 3) * 2;
            const float b0 = bias[col];
            const float b1 = bias[col + 1];
            float2 v0 = make_float2(acc[mi][ni][0] + b0, acc[mi][ni][1] + b1);
            float2 v1 = make_float2(acc[mi][ni][2] + b0, acc[mi][ni][3] + b1);
            *(float2*)&C[(size_t)row0 * N_TOTAL + col]       = v0;
            *(float2*)&C[(size_t)(row0 + 8) * N_TOTAL + col] = v1;
        }
    }
}

// ---------------------------------------------------------------------------
// Launch
// ---------------------------------------------------------------------------
extern "C" void kernel_launch(void* const* d_in, const int* in_sizes, int n_in,
                              void* d_out, int out_size) {
    const float* x     = (const float*)d_in[0];
    const int*   wp    = (const int*)d_in[1];
    const float* scale = (const float*)d_in[2];
    const float* bias  = (const float*)d_in[3];
    float*       out   = (float*)d_out;

    __half* xh = nullptr;
    __half* wh = nullptr;
    cudaGetSymbolAddress((void**)&xh, g_Xh);
    cudaGetSymbolAddress((void**)&wh, g_Wh);

    prep_kernel<<<XB + WB, 256>>>(x, wp, scale, xh, wh);

    cudaFuncSetAttribute(gemm_f16_kernel,
                         cudaFuncAttributeMaxDynamicSharedMemorySize, SMEM_TOTAL);
    dim3 grid(N_TOTAL / BN, M_TOTAL / BM);   // (32, 128)
    gemm_f16_kernel<<<grid, 160, SMEM_TOTAL>>>(xh, wh, bias, out);
}